// round 15
// baseline (speedup 1.0000x reference)
#include <cuda_runtime.h>
#include <cuda_fp16.h>
#include <cstdint>
#include <math.h>

#define BATCH 32
#define NN    2000
#define EMB   64

// scratch
__device__ __half g_Qh[BATCH * NN * EMB];  // LN q, fp16, cols interleave-permuted
__device__ __half g_Kh[BATCH * NN * EMB];  // LN k, fp16, cols interleave-permuted
__device__ __half g_VTh[384 * 2048];       // normal^T fp16, keys perm, >=2000 zero

// ===========================================================================
// helpers
// ===========================================================================
__device__ __forceinline__ uint32_t smem_u32(const void* p) {
    uint32_t a;
    asm("{ .reg .u64 t; cvta.to.shared.u64 t, %1; cvt.u32.u64 %0, t; }" : "=r"(a) : "l"(p));
    return a;
}
__device__ __forceinline__ void cp_async16(uint32_t dst, const void* src, bool pred) {
    int sz = pred ? 16 : 0;
    asm volatile("cp.async.cg.shared.global [%0], [%1], 16, %2;\n"
                 :: "r"(dst), "l"(src), "r"(sz));
}
__device__ __forceinline__ void cp_commit() { asm volatile("cp.async.commit_group;"); }
__device__ __forceinline__ void cp_wait0()  { asm volatile("cp.async.wait_group 0;" ::: "memory"); }

__device__ __forceinline__ uint32_t to_tf32(float f) {
    uint32_t r;
    asm("cvt.rna.tf32.f32 %0, %1;" : "=r"(r) : "f"(f));
    return r;
}
__device__ __forceinline__ uint32_t pack_f16(float lo, float hi) {
    uint32_t r;
    asm("cvt.rn.f16x2.f32 %0, %1, %2;" : "=r"(r) : "f"(hi), "f"(lo));
    return r;
}

// tf32: D += A(16x8) B(8x8)
__device__ __forceinline__ void mma16n8k8(float* d,
    uint32_t a0, uint32_t a1, uint32_t a2, uint32_t a3,
    uint32_t b0, uint32_t b1)
{
    asm volatile("mma.sync.aligned.m16n8k8.row.col.f32.tf32.tf32.f32 "
        "{%0,%1,%2,%3}, {%4,%5,%6,%7}, {%8,%9}, {%0,%1,%2,%3};"
        : "+f"(d[0]), "+f"(d[1]), "+f"(d[2]), "+f"(d[3])
        : "r"(a0), "r"(a1), "r"(a2), "r"(a3), "r"(b0), "r"(b1));
}
// fp16: D(f32) += A(16x16 f16) B(16x8 f16)
__device__ __forceinline__ void mma16n8k16h(float* d,
    uint32_t a0, uint32_t a1, uint32_t a2, uint32_t a3,
    uint32_t b0, uint32_t b1)
{
    asm volatile("mma.sync.aligned.m16n8k16.row.col.f32.f16.f16.f32 "
        "{%0,%1,%2,%3}, {%4,%5,%6,%7}, {%8,%9}, {%0,%1,%2,%3};"
        : "+f"(d[0]), "+f"(d[1]), "+f"(d[2]), "+f"(d[3])
        : "r"(a0), "r"(a1), "r"(a2), "r"(a3), "r"(b0), "r"(b1));
}

// interleave permutation within 16-groups: [0,1,8,9,2,3,10,11,4,5,12,13,6,7,14,15]
__device__ __forceinline__ int perm16(int o) {
    return (o & ~15) | ((((o & 7) >> 1) << 2) | (((o >> 3) & 1) << 1) | (o & 1));
}

// ===========================================================================
// Kernel 1: q = LN(xf@Wq+bq), k = LN(xf@Wk+bk) on tensor cores (tf32 inside,
// fp16 permuted outputs). CTA = 64 rows x 128 outs, 8 chunks of 48, occ 2.
// ===========================================================================
#define KP_XSTR 52
#define KP_WSTR 132
#define KP_XBUF (64 * KP_XSTR)
#define KP_WBUF (48 * KP_WSTR)
#define KP_XS   0
#define KP_WS   6656
#define KP_PB   19328
#define KP_PG   19456
#define KP_PBE  19584
#define KP_SMF  19712
#define KP_SMEM (KP_SMF * 4)

__global__ __launch_bounds__(256, 2) void k_proj_mma(
    const float* __restrict__ x,
    const float* __restrict__ Wq, const float* __restrict__ bq,
    const float* __restrict__ Wk, const float* __restrict__ bk,
    const float* __restrict__ g0, const float* __restrict__ be0,
    const float* __restrict__ g1, const float* __restrict__ be1)
{
    extern __shared__ float sp[];
    const uint32_t sb = smem_u32(sp);
    const int tid  = threadIdx.x;
    const int w    = tid >> 5;
    const int lane = tid & 31;
    const int g    = lane >> 2;
    const int c    = lane & 3;
    const int rw   = w & 3,  ow = w >> 2;
    const int rbase = rw * 16;
    const int n0    = ow * 64;
    const long R0 = (long)blockIdx.x * 64;

    if (tid < 128) {
        int o = tid;
        sp[KP_PB  + o] = (o < 64) ? bq[o]  : bk[o - 64];
        sp[KP_PG  + o] = (o < 64) ? g0[o]  : g1[o - 64];
        sp[KP_PBE + o] = (o < 64) ? be0[o] : be1[o - 64];
    }

#pragma unroll
    for (int p = 0; p < 3; p++) {
        int idx = tid + 256 * p;
        int row = idx / 12, qd = idx % 12;
        cp_async16(sb + (KP_XS + row * KP_XSTR + qd * 4) * 4,
                   &x[(R0 + row) * 384 + qd * 4], true);
    }
#pragma unroll
    for (int p = 0; p < 6; p++) {
        int idx = tid + 256 * p;
        int k = idx >> 5, qd = idx & 31;
        const float* src = (qd < 16) ? &Wq[(size_t)k * 64 + qd * 4]
                                     : &Wk[(size_t)k * 64 + (qd - 16) * 4];
        cp_async16(sb + (KP_WS + k * KP_WSTR + qd * 4) * 4, src, true);
    }
    cp_commit();

    float d[8][4];
#pragma unroll
    for (int t = 0; t < 8; t++)
#pragma unroll
        for (int j = 0; j < 4; j++) d[t][j] = 0.f;

    for (int ch = 0; ch < 8; ch++) {
        cp_wait0();
        __syncthreads();

        if (ch < 7) {
            const int nb = (ch + 1) & 1;
            const int kc = (ch + 1) * 48;
#pragma unroll
            for (int p = 0; p < 3; p++) {
                int idx = tid + 256 * p;
                int row = idx / 12, qd = idx % 12;
                cp_async16(sb + (KP_XS + nb * KP_XBUF + row * KP_XSTR + qd * 4) * 4,
                           &x[(R0 + row) * 384 + kc + qd * 4], true);
            }
#pragma unroll
            for (int p = 0; p < 6; p++) {
                int idx = tid + 256 * p;
                int k = idx >> 5, qd = idx & 31;
                const float* src = (qd < 16) ? &Wq[(size_t)(kc + k) * 64 + qd * 4]
                                             : &Wk[(size_t)(kc + k) * 64 + (qd - 16) * 4];
                cp_async16(sb + (KP_WS + nb * KP_WBUF + k * KP_WSTR + qd * 4) * 4, src, true);
            }
            cp_commit();
        }

        const float* xs = sp + KP_XS + (ch & 1) * KP_XBUF;
        const float* ws = sp + KP_WS + (ch & 1) * KP_WBUF;

#pragma unroll
        for (int ks = 0; ks < 6; ks++) {
            const int kk = ks * 8;
            uint32_t a0 = to_tf32(xs[(rbase + g)     * KP_XSTR + kk + c]);
            uint32_t a1 = to_tf32(xs[(rbase + g + 8) * KP_XSTR + kk + c]);
            uint32_t a2 = to_tf32(xs[(rbase + g)     * KP_XSTR + kk + c + 4]);
            uint32_t a3 = to_tf32(xs[(rbase + g + 8) * KP_XSTR + kk + c + 4]);
#pragma unroll
            for (int nt = 0; nt < 8; nt++) {
                uint32_t b0 = to_tf32(ws[(kk + c)     * KP_WSTR + n0 + nt * 8 + g]);
                uint32_t b1 = to_tf32(ws[(kk + c + 4) * KP_WSTR + n0 + nt * 8 + g]);
                mma16n8k8(d[nt], a0, a1, a2, a3, b0, b1);
            }
        }
    }

    // epilogue: bias + LN + fp16 permuted store
    float v[8][4];
    float s0 = 0.f, q0 = 0.f, s1 = 0.f, q1 = 0.f;
#pragma unroll
    for (int nt = 0; nt < 8; nt++)
#pragma unroll
        for (int j = 0; j < 4; j++) {
            int col = n0 + nt * 8 + 2 * c + (j & 1);
            float t = d[nt][j] + sp[KP_PB + col];
            v[nt][j] = t;
            if (j < 2) { s0 += t; q0 += t * t; }
            else       { s1 += t; q1 += t * t; }
        }
#pragma unroll
    for (int m = 1; m <= 2; m <<= 1) {
        s0 += __shfl_xor_sync(0xffffffffu, s0, m);
        q0 += __shfl_xor_sync(0xffffffffu, q0, m);
        s1 += __shfl_xor_sync(0xffffffffu, s1, m);
        q1 += __shfl_xor_sync(0xffffffffu, q1, m);
    }
    const float mu0 = s0 * (1.f / 64.f);
    const float r0v = rsqrtf(q0 * (1.f / 64.f) - mu0 * mu0 + 1e-5f);
    const float mu1 = s1 * (1.f / 64.f);
    const float r1v = rsqrtf(q1 * (1.f / 64.f) - mu1 * mu1 + 1e-5f);

    __half* dst = ow ? g_Kh : g_Qh;
    const long base0 = (R0 + rbase + g) * 64;
    const long base1 = base0 + 8 * 64;
#pragma unroll
    for (int nt = 0; nt < 8; nt++)
#pragma unroll
        for (int par = 0; par < 2; par++) {
            int o   = nt * 8 + 2 * c + par;
            int col = n0 + o;
            int pos = perm16(o);
            float gv = sp[KP_PG + col], bev = sp[KP_PBE + col];
            dst[base0 + pos] = __float2half((v[nt][par]     - mu0) * r0v * gv + bev);
            dst[base1 + pos] = __float2half((v[nt][2 + par] - mu1) * r1v * gv + bev);
        }
}

// ===========================================================================
// Kernel 1b: transpose normal -> g_VTh (384 x 2048 fp16), key-permuted, pad 0
// ===========================================================================
__global__ __launch_bounds__(256) void k_transpose(const float* __restrict__ normal)
{
    __shared__ float t[32][33];
    const int m0 = blockIdx.x * 32;
    const int c0 = blockIdx.y * 32;
    const int tx = threadIdx.x & 31, ty = threadIdx.x >> 5;
#pragma unroll
    for (int p = 0; p < 4; p++) {
        int m = m0 + ty + 8 * p;
        t[ty + 8 * p][tx] = (m < NN) ? normal[(long)m * 384 + c0 + tx] : 0.f;
    }
    __syncthreads();
    const int pm = perm16(tx);
#pragma unroll
    for (int p = 0; p < 4; p++) {
        int c = c0 + ty + 8 * p;
        g_VTh[(long)c * 2048 + m0 + pm] = __float2half(t[tx][ty + 8 * p]);
    }
}

// ===========================================================================
// Kernel 2: flash node-attention, fp16 mma m16n8k16, 64-key chunks (32
// barriers instead of 63). grid (16 x 2 x 32), 256 threads, occ 1.
// ===========================================================================
#define CHK    64
#define NCHUNK 32            // 32*64 = 2048 >= 2000
#define QSTR_H 72            // halves (64 data + 8 pad)
#define VSTR_H 72            // halves (64 keys + 8 pad)
#define NSLC   192

#define QS_H  0                            // 128*72 = 9216 h
#define KS_H  (128 * QSTR_H)               // 2*64*72 = 9216 h
#define VT_H  (KS_H + 2 * CHK * QSTR_H)    // 2*192*72 = 27648 h
#define SMH   (VT_H + 2 * NSLC * VSTR_H)   // 46080 halves
#define SMEM_SZ (SMH * 2)                  // 92160 bytes

__global__ __launch_bounds__(256, 1) void k_attn_mma(float* __restrict__ out)
{
    extern __shared__ __half smh[];
    const uint32_t sb = smem_u32(smh);
    const int tid  = threadIdx.x;
    const int w    = tid >> 5;
    const int lane = tid & 31;
    const int g    = lane >> 2;
    const int c    = lane & 3;
    const int mt = blockIdx.x, ns = blockIdx.y, b = blockIdx.z;
    const int n0 = mt * 128;
    const int mr = w * 16;
    const float SCALE = 0.02236067977f;
    const long qrow0 = (long)b * NN;

    // ---- initial loads: Q tile + chunk 0 K/V ----
#pragma unroll
    for (int p = 0; p < 4; p++) {                  // Q: 128 rows x 8 quads
        int idx = tid + 256 * p;
        int row = idx >> 3, q = idx & 7;
        cp_async16(sb + (row * QSTR_H + q * 8) * 2,
                   &g_Qh[(qrow0 + n0 + row) * 64 + q * 8], (n0 + row) < NN);
    }
#pragma unroll
    for (int p = 0; p < 2; p++) {                  // K chunk0: 64 rows x 8 quads
        int idx = tid + 256 * p;
        int row = idx >> 3, q = idx & 7;
        cp_async16(sb + (KS_H + row * QSTR_H + q * 8) * 2,
                   &g_Kh[(qrow0 + row) * 64 + q * 8], row < NN);
    }
#pragma unroll
    for (int p = 0; p < 6; p++) {                  // Vt chunk0: 192 rows x 8 quads
        int idx = tid + 256 * p;
        int n = idx >> 3, q = idx & 7;
        cp_async16(sb + (VT_H + n * VSTR_H + q * 8) * 2,
                   &g_VTh[(size_t)(ns * NSLC + n) * 2048 + q * 8], true);
    }
    cp_commit();
    cp_wait0();
    __syncthreads();

    // ---- Q fragments -> registers ----
    uint32_t qa[4][4];
    {
        const uint2* q0 = (const uint2*)(smh + (mr + g) * QSTR_H);
        const uint2* q1 = (const uint2*)(smh + (mr + g + 8) * QSTR_H);
#pragma unroll
        for (int ks = 0; ks < 4; ks++) {
            uint2 x0 = q0[ks * 4 + c];
            uint2 x1 = q1[ks * 4 + c];
            qa[ks][0] = x0.x;
            qa[ks][1] = x1.x;
            qa[ks][2] = x0.y;
            qa[ks][3] = x1.y;
        }
    }

    float d[24][4];
#pragma unroll
    for (int t = 0; t < 24; t++)
#pragma unroll
        for (int j = 0; j < 4; j++) d[t][j] = 0.f;
    float rs0 = 0.f, rs1 = 0.f;

    for (int i = 0; i < NCHUNK; i++) {
        const int buf = i & 1;

        if (i + 1 < NCHUNK) {
            const int nb = 1 - buf;
            const int k0 = (i + 1) * CHK;
#pragma unroll
            for (int p = 0; p < 2; p++) {
                int idx = tid + 256 * p;
                int row = idx >> 3, q = idx & 7;
                cp_async16(sb + (KS_H + nb * CHK * QSTR_H + row * QSTR_H + q * 8) * 2,
                           &g_Kh[(qrow0 + k0 + row) * 64 + q * 8], (k0 + row) < NN);
            }
#pragma unroll
            for (int p = 0; p < 6; p++) {
                int idx = tid + 256 * p;
                int n = idx >> 3, q = idx & 7;
                cp_async16(sb + (VT_H + nb * NSLC * VSTR_H + n * VSTR_H + q * 8) * 2,
                           &g_VTh[(size_t)(ns * NSLC + n) * 2048 + k0 + q * 8], true);
            }
            cp_commit();
        }

        // ---- mma1: S = Q K^T  (4 k-groups x 8 n-tiles of 8 keys) ----
        const uint2* Kp = (const uint2*)(smh + KS_H + buf * CHK * QSTR_H);
        float s[8][4];
#pragma unroll
        for (int t = 0; t < 8; t++)
#pragma unroll
            for (int j = 0; j < 4; j++) s[t][j] = 0.f;

#pragma unroll
        for (int ks = 0; ks < 4; ks++) {
#pragma unroll
            for (int nt = 0; nt < 8; nt++) {
                uint2 kb = Kp[(8 * nt + g) * (QSTR_H / 4) + ks * 4 + c];
                mma16n8k16h(s[nt], qa[ks][0], qa[ks][1], qa[ks][2], qa[ks][3],
                            kb.x, kb.y);
            }
        }

        // ---- fused exp + rowsum + mma2 (P: C-frag -> A-frag, in regs) ----
        const uint2* Vp = (const uint2*)(smh + VT_H + buf * NSLC * VSTR_H);
#pragma unroll
        for (int ks2 = 0; ks2 < 4; ks2++) {
            const int t0 = 2 * ks2, t1 = t0 + 1;
            float p00 = __expf(s[t0][0] * SCALE);
            float p01 = __expf(s[t0][1] * SCALE);
            float p02 = __expf(s[t0][2] * SCALE);
            float p03 = __expf(s[t0][3] * SCALE);
            float p10 = __expf(s[t1][0] * SCALE);
            float p11 = __expf(s[t1][1] * SCALE);
            float p12 = __expf(s[t1][2] * SCALE);
            float p13 = __expf(s[t1][3] * SCALE);
            if (i == NCHUNK - 1) {
                int kc0 = i * CHK + 8 * t0 + 2 * c;
                int kc1 = i * CHK + 8 * t1 + 2 * c;
                if (kc0     >= NN) { p00 = 0.f; p02 = 0.f; }
                if (kc0 + 1 >= NN) { p01 = 0.f; p03 = 0.f; }
                if (kc1     >= NN) { p10 = 0.f; p12 = 0.f; }
                if (kc1 + 1 >= NN) { p11 = 0.f; p13 = 0.f; }
            }
            rs0 += p00 + p01 + p10 + p11;
            rs1 += p02 + p03 + p12 + p13;
            uint32_t a0 = pack_f16(p00, p01);
            uint32_t a1 = pack_f16(p02, p03);
            uint32_t a2 = pack_f16(p10, p11);
            uint32_t a3 = pack_f16(p12, p13);
#pragma unroll
            for (int nt = 0; nt < 24; nt++) {
                uint2 vb = Vp[(8 * nt + g) * (VSTR_H / 4) + ks2 * 4 + c];
                mma16n8k16h(d[nt], a0, a1, a2, a3, vb.x, vb.y);
            }
        }

        cp_wait0();
        __syncthreads();
    }

    // ---- epilogue ----
    rs0 += __shfl_xor_sync(0xffffffffu, rs0, 1);
    rs0 += __shfl_xor_sync(0xffffffffu, rs0, 2);
    rs1 += __shfl_xor_sync(0xffffffffu, rs1, 1);
    rs1 += __shfl_xor_sync(0xffffffffu, rs1, 2);
    const float inv0 = 1.f / rs0, inv1 = 1.f / rs1;

    const int r0 = n0 + mr + g;
    const int r1 = r0 + 8;
    float* o0 = out + (qrow0 + r0) * 384 + ns * NSLC + 2 * c;
    float* o1 = out + (qrow0 + r1) * 384 + ns * NSLC + 2 * c;
#pragma unroll
    for (int nt = 0; nt < 24; nt++) {
        if (r0 < NN) *(float2*)(o0 + 8 * nt) = make_float2(d[nt][0] * inv0, d[nt][1] * inv0);
        if (r1 < NN) *(float2*)(o1 + 8 * nt) = make_float2(d[nt][2] * inv1, d[nt][3] * inv1);
    }
}

// ===========================================================================
// Kernel 3: time-attention + broadcast add, vectorized (1 read + 1 write of
// each row, all float4). Deterministic (no float atomics).
// ===========================================================================
__global__ __launch_bounds__(256) void k_time(
    const float* __restrict__ x, const float* __restrict__ Win,
    float* __restrict__ out)
{
    const int wid = threadIdx.x >> 5, lane = threadIdx.x & 31;
    const long node = (long)blockIdx.x * 8 + wid;
    __shared__ float qs[8][16];
    __shared__ float sp[8][97];    // 96 partials + pad

    const float* xl = x + node * 384 + 368;
    float4* dat4 = (float4*)(out + node * 384);

    if (lane < 16) {
        float q = 0.f;
#pragma unroll
        for (int d = 0; d < 16; d++) q += xl[d] * Win[d * 16 + lane];
        qs[wid][lane] = q;
    }
    __syncwarp();

    // each lane: 3 float4 (kept in regs), partial dot vs q
    float4 v[3];
#pragma unroll
    for (int p = 0; p < 3; p++) {
        int idx = 3 * lane + p;
        v[p] = dat4[idx];
        int db = (idx & 3) * 4;
        sp[wid][idx] = v[p].x * qs[wid][db]     + v[p].y * qs[wid][db + 1]
                     + v[p].z * qs[wid][db + 2] + v[p].w * qs[wid][db + 3];
    }
    __syncwarp();

    // att[t] = sum of 4 partials (deterministic order)
    float att = -1e30f;
    if (lane < 24) {
        const float* pp = &sp[wid][lane * 4];
        att = (pp[0] + pp[1]) + (pp[2] + pp[3]);
    }
    float mx = att;
#pragma unroll
    for (int m = 16; m >= 1; m >>= 1)
        mx = fmaxf(mx, __shfl_xor_sync(0xffffffffu, mx, m));
    float e = (lane < 24) ? __expf(att - mx) : 0.f;
    float s = e;
#pragma unroll
    for (int m = 16; m >= 1; m >>= 1)
        s += __shfl_xor_sync(0xffffffffu, s, m);
    float wgt = e / s;

#pragma unroll
    for (int p = 0; p < 3; p++) {
        int idx = 3 * lane + p;
        float wt = __shfl_sync(0xffffffffu, wgt, idx >> 2);
        dat4[idx] = make_float4(v[p].x + wt, v[p].y + wt, v[p].z + wt, v[p].w + wt);
    }
}

// ===========================================================================
extern "C" void kernel_launch(void* const* d_in, const int* in_sizes, int n_in,
                              void* d_out, int out_size)
{
    const float* x      = (const float*)d_in[0];
    const float* Wq     = (const float*)d_in[1];
    const float* bq     = (const float*)d_in[2];
    const float* Wk     = (const float*)d_in[3];
    const float* bk     = (const float*)d_in[4];
    const float* g0     = (const float*)d_in[5];
    const float* be0    = (const float*)d_in[6];
    const float* g1     = (const float*)d_in[7];
    const float* be1    = (const float*)d_in[8];
    const float* normal = (const float*)d_in[9];
    const float* Win    = (const float*)d_in[10];
    float* out = (float*)d_out;

    cudaFuncSetAttribute(k_proj_mma, cudaFuncAttributeMaxDynamicSharedMemorySize, KP_SMEM);
    cudaFuncSetAttribute(k_attn_mma, cudaFuncAttributeMaxDynamicSharedMemorySize, SMEM_SZ);

    k_proj_mma<<<(BATCH * NN) / 64, 256, KP_SMEM>>>(x, Wq, bq, Wk, bk, g0, be0, g1, be1);
    k_transpose<<<dim3(64, 12), 256>>>(normal);
    k_attn_mma<<<dim3(16, 2, BATCH), 256, SMEM_SZ>>>(out);
    k_time<<<(BATCH * NN) / 8, 256>>>(x, Win, out);
}

// round 16
// speedup vs baseline: 1.4923x; 1.4923x over previous
#include <cuda_runtime.h>
#include <cuda_fp16.h>
#include <cstdint>
#include <math.h>

#define BATCH 32
#define NN    2000
#define EMB   64

// scratch
__device__ __half g_Qh[BATCH * NN * EMB];  // LN q, fp16, cols interleave-permuted
__device__ __half g_Kh[BATCH * NN * EMB];  // LN k, fp16, cols interleave-permuted
__device__ __half g_VTh[384 * 2048];       // normal^T fp16, keys perm, >=2000 zero

// ===========================================================================
// helpers
// ===========================================================================
__device__ __forceinline__ uint32_t smem_u32(const void* p) {
    uint32_t a;
    asm("{ .reg .u64 t; cvta.to.shared.u64 t, %1; cvt.u32.u64 %0, t; }" : "=r"(a) : "l"(p));
    return a;
}
__device__ __forceinline__ void cp_async16(uint32_t dst, const void* src, bool pred) {
    int sz = pred ? 16 : 0;
    asm volatile("cp.async.cg.shared.global [%0], [%1], 16, %2;\n"
                 :: "r"(dst), "l"(src), "r"(sz));
}
__device__ __forceinline__ void cp_commit() { asm volatile("cp.async.commit_group;"); }
__device__ __forceinline__ void cp_wait0()  { asm volatile("cp.async.wait_group 0;" ::: "memory"); }

__device__ __forceinline__ uint32_t to_tf32(float f) {
    uint32_t r;
    asm("cvt.rna.tf32.f32 %0, %1;" : "=r"(r) : "f"(f));
    return r;
}
__device__ __forceinline__ uint32_t pack_f16(float lo, float hi) {
    uint32_t r;
    asm("cvt.rn.f16x2.f32 %0, %1, %2;" : "=r"(r) : "f"(hi), "f"(lo));
    return r;
}

// tf32: D += A(16x8) B(8x8)
__device__ __forceinline__ void mma16n8k8(float* d,
    uint32_t a0, uint32_t a1, uint32_t a2, uint32_t a3,
    uint32_t b0, uint32_t b1)
{
    asm volatile("mma.sync.aligned.m16n8k8.row.col.f32.tf32.tf32.f32 "
        "{%0,%1,%2,%3}, {%4,%5,%6,%7}, {%8,%9}, {%0,%1,%2,%3};"
        : "+f"(d[0]), "+f"(d[1]), "+f"(d[2]), "+f"(d[3])
        : "r"(a0), "r"(a1), "r"(a2), "r"(a3), "r"(b0), "r"(b1));
}
// fp16: D(f32) += A(16x16 f16) B(16x8 f16)
__device__ __forceinline__ void mma16n8k16h(float* d,
    uint32_t a0, uint32_t a1, uint32_t a2, uint32_t a3,
    uint32_t b0, uint32_t b1)
{
    asm volatile("mma.sync.aligned.m16n8k16.row.col.f32.f16.f16.f32 "
        "{%0,%1,%2,%3}, {%4,%5,%6,%7}, {%8,%9}, {%0,%1,%2,%3};"
        : "+f"(d[0]), "+f"(d[1]), "+f"(d[2]), "+f"(d[3])
        : "r"(a0), "r"(a1), "r"(a2), "r"(a3), "r"(b0), "r"(b1));
}

// interleave permutation within 16-groups: [0,1,8,9,2,3,10,11,4,5,12,13,6,7,14,15]
__device__ __forceinline__ int perm16(int o) {
    return (o & ~15) | ((((o & 7) >> 1) << 2) | (((o >> 3) & 1) << 1) | (o & 1));
}

// ===========================================================================
// Kernel 1: q = LN(xf@Wq+bq), k = LN(xf@Wk+bk) on tensor cores (tf32 inside,
// fp16 permuted outputs). CTA = 64 rows x 128 outs, 8 chunks of 48, occ 2.
// ===========================================================================
#define KP_XSTR 52
#define KP_WSTR 132
#define KP_XBUF (64 * KP_XSTR)
#define KP_WBUF (48 * KP_WSTR)
#define KP_XS   0
#define KP_WS   6656
#define KP_PB   19328
#define KP_PG   19456
#define KP_PBE  19584
#define KP_SMF  19712
#define KP_SMEM (KP_SMF * 4)

__global__ __launch_bounds__(256, 2) void k_proj_mma(
    const float* __restrict__ x,
    const float* __restrict__ Wq, const float* __restrict__ bq,
    const float* __restrict__ Wk, const float* __restrict__ bk,
    const float* __restrict__ g0, const float* __restrict__ be0,
    const float* __restrict__ g1, const float* __restrict__ be1)
{
    extern __shared__ float sp[];
    const uint32_t sb = smem_u32(sp);
    const int tid  = threadIdx.x;
    const int w    = tid >> 5;
    const int lane = tid & 31;
    const int g    = lane >> 2;
    const int c    = lane & 3;
    const int rw   = w & 3,  ow = w >> 2;
    const int rbase = rw * 16;
    const int n0    = ow * 64;
    const long R0 = (long)blockIdx.x * 64;

    if (tid < 128) {
        int o = tid;
        sp[KP_PB  + o] = (o < 64) ? bq[o]  : bk[o - 64];
        sp[KP_PG  + o] = (o < 64) ? g0[o]  : g1[o - 64];
        sp[KP_PBE + o] = (o < 64) ? be0[o] : be1[o - 64];
    }

#pragma unroll
    for (int p = 0; p < 3; p++) {
        int idx = tid + 256 * p;
        int row = idx / 12, qd = idx % 12;
        cp_async16(sb + (KP_XS + row * KP_XSTR + qd * 4) * 4,
                   &x[(R0 + row) * 384 + qd * 4], true);
    }
#pragma unroll
    for (int p = 0; p < 6; p++) {
        int idx = tid + 256 * p;
        int k = idx >> 5, qd = idx & 31;
        const float* src = (qd < 16) ? &Wq[(size_t)k * 64 + qd * 4]
                                     : &Wk[(size_t)k * 64 + (qd - 16) * 4];
        cp_async16(sb + (KP_WS + k * KP_WSTR + qd * 4) * 4, src, true);
    }
    cp_commit();

    float d[8][4];
#pragma unroll
    for (int t = 0; t < 8; t++)
#pragma unroll
        for (int j = 0; j < 4; j++) d[t][j] = 0.f;

    for (int ch = 0; ch < 8; ch++) {
        cp_wait0();
        __syncthreads();

        if (ch < 7) {
            const int nb = (ch + 1) & 1;
            const int kc = (ch + 1) * 48;
#pragma unroll
            for (int p = 0; p < 3; p++) {
                int idx = tid + 256 * p;
                int row = idx / 12, qd = idx % 12;
                cp_async16(sb + (KP_XS + nb * KP_XBUF + row * KP_XSTR + qd * 4) * 4,
                           &x[(R0 + row) * 384 + kc + qd * 4], true);
            }
#pragma unroll
            for (int p = 0; p < 6; p++) {
                int idx = tid + 256 * p;
                int k = idx >> 5, qd = idx & 31;
                const float* src = (qd < 16) ? &Wq[(size_t)(kc + k) * 64 + qd * 4]
                                             : &Wk[(size_t)(kc + k) * 64 + (qd - 16) * 4];
                cp_async16(sb + (KP_WS + nb * KP_WBUF + k * KP_WSTR + qd * 4) * 4, src, true);
            }
            cp_commit();
        }

        const float* xs = sp + KP_XS + (ch & 1) * KP_XBUF;
        const float* ws = sp + KP_WS + (ch & 1) * KP_WBUF;

#pragma unroll
        for (int ks = 0; ks < 6; ks++) {
            const int kk = ks * 8;
            uint32_t a0 = to_tf32(xs[(rbase + g)     * KP_XSTR + kk + c]);
            uint32_t a1 = to_tf32(xs[(rbase + g + 8) * KP_XSTR + kk + c]);
            uint32_t a2 = to_tf32(xs[(rbase + g)     * KP_XSTR + kk + c + 4]);
            uint32_t a3 = to_tf32(xs[(rbase + g + 8) * KP_XSTR + kk + c + 4]);
#pragma unroll
            for (int nt = 0; nt < 8; nt++) {
                uint32_t b0 = to_tf32(ws[(kk + c)     * KP_WSTR + n0 + nt * 8 + g]);
                uint32_t b1 = to_tf32(ws[(kk + c + 4) * KP_WSTR + n0 + nt * 8 + g]);
                mma16n8k8(d[nt], a0, a1, a2, a3, b0, b1);
            }
        }
    }

    // epilogue: bias + LN + fp16 permuted store
    float v[8][4];
    float s0 = 0.f, q0 = 0.f, s1 = 0.f, q1 = 0.f;
#pragma unroll
    for (int nt = 0; nt < 8; nt++)
#pragma unroll
        for (int j = 0; j < 4; j++) {
            int col = n0 + nt * 8 + 2 * c + (j & 1);
            float t = d[nt][j] + sp[KP_PB + col];
            v[nt][j] = t;
            if (j < 2) { s0 += t; q0 += t * t; }
            else       { s1 += t; q1 += t * t; }
        }
#pragma unroll
    for (int m = 1; m <= 2; m <<= 1) {
        s0 += __shfl_xor_sync(0xffffffffu, s0, m);
        q0 += __shfl_xor_sync(0xffffffffu, q0, m);
        s1 += __shfl_xor_sync(0xffffffffu, s1, m);
        q1 += __shfl_xor_sync(0xffffffffu, q1, m);
    }
    const float mu0 = s0 * (1.f / 64.f);
    const float r0v = rsqrtf(q0 * (1.f / 64.f) - mu0 * mu0 + 1e-5f);
    const float mu1 = s1 * (1.f / 64.f);
    const float r1v = rsqrtf(q1 * (1.f / 64.f) - mu1 * mu1 + 1e-5f);

    __half* dst = ow ? g_Kh : g_Qh;
    const long base0 = (R0 + rbase + g) * 64;
    const long base1 = base0 + 8 * 64;
#pragma unroll
    for (int nt = 0; nt < 8; nt++)
#pragma unroll
        for (int par = 0; par < 2; par++) {
            int o   = nt * 8 + 2 * c + par;
            int col = n0 + o;
            int pos = perm16(o);
            float gv = sp[KP_PG + col], bev = sp[KP_PBE + col];
            dst[base0 + pos] = __float2half((v[nt][par]     - mu0) * r0v * gv + bev);
            dst[base1 + pos] = __float2half((v[nt][2 + par] - mu1) * r1v * gv + bev);
        }
}

// ===========================================================================
// Kernel 1b: transpose normal -> g_VTh (384 x 2048 fp16), key-permuted, pad 0
// ===========================================================================
__global__ __launch_bounds__(256) void k_transpose(const float* __restrict__ normal)
{
    __shared__ float t[32][33];
    const int m0 = blockIdx.x * 32;
    const int c0 = blockIdx.y * 32;
    const int tx = threadIdx.x & 31, ty = threadIdx.x >> 5;
#pragma unroll
    for (int p = 0; p < 4; p++) {
        int m = m0 + ty + 8 * p;
        t[ty + 8 * p][tx] = (m < NN) ? normal[(long)m * 384 + c0 + tx] : 0.f;
    }
    __syncthreads();
    const int pm = perm16(tx);
#pragma unroll
    for (int p = 0; p < 4; p++) {
        int c = c0 + ty + 8 * p;
        g_VTh[(long)c * 2048 + m0 + pm] = __float2half(t[tx][ty + 8 * p]);
    }
}

// ===========================================================================
// Kernel 2: flash node-attention, fp16 mma.sync m16n8k16, 32-key chunks
// (R13 proven config: no spills). grid (16 x 2 x 32), 256 threads, occ 1.
// ===========================================================================
#define CHK    32
#define NCHUNK 63
#define QSTR_H 72            // halves (64 data + 8 pad)
#define VSTR_H 40            // halves (32 keys + 8 pad)
#define NSLC   192

#define QS_H  0                            // 128*72 = 9216 h
#define KS_H  (128 * QSTR_H)               // 2*32*72 = 4608 h
#define VT_H  (KS_H + 2 * CHK * QSTR_H)    // 2*192*40 = 15360 h
#define SMH   (VT_H + 2 * NSLC * VSTR_H)   // 29184 halves
#define SMEM_SZ (SMH * 2)                  // 58368 bytes

__global__ __launch_bounds__(256, 1) void k_attn_mma(float* __restrict__ out)
{
    extern __shared__ __half smh[];
    const uint32_t sb = smem_u32(smh);
    const int tid  = threadIdx.x;
    const int w    = tid >> 5;
    const int lane = tid & 31;
    const int g    = lane >> 2;
    const int c    = lane & 3;
    const int mt = blockIdx.x, ns = blockIdx.y, b = blockIdx.z;
    const int n0 = mt * 128;
    const int mr = w * 16;
    const float SCALE = 0.02236067977f;
    const long qrow0 = (long)b * NN;

    // ---- initial loads: Q tile + chunk 0 K/V ----
#pragma unroll
    for (int p = 0; p < 4; p++) {                  // Q: 128 rows x 8 quads
        int idx = tid + 256 * p;
        int row = idx >> 3, q = idx & 7;
        cp_async16(sb + (row * QSTR_H + q * 8) * 2,
                   &g_Qh[(qrow0 + n0 + row) * 64 + q * 8], (n0 + row) < NN);
    }
    {                                              // K chunk0: 32 rows x 8 quads
        int row = tid >> 3, q = tid & 7;
        cp_async16(sb + (KS_H + row * QSTR_H + q * 8) * 2,
                   &g_Kh[(qrow0 + row) * 64 + q * 8], row < NN);
    }
#pragma unroll
    for (int p = 0; p < 3; p++) {                  // Vt chunk0: 192 rows x 4 quads
        int idx = tid + 256 * p;
        int n = idx >> 2, q = idx & 3;
        cp_async16(sb + (VT_H + n * VSTR_H + q * 8) * 2,
                   &g_VTh[(size_t)(ns * NSLC + n) * 2048 + q * 8], true);
    }
    cp_commit();
    cp_wait0();
    __syncthreads();

    // ---- Q fragments -> registers (4 k-groups of 16) ----
    uint32_t qa[4][4];
    {
        const uint2* q0 = (const uint2*)(smh + (mr + g) * QSTR_H);
        const uint2* q1 = (const uint2*)(smh + (mr + g + 8) * QSTR_H);
#pragma unroll
        for (int ks = 0; ks < 4; ks++) {
            uint2 x0 = q0[ks * 4 + c];
            uint2 x1 = q1[ks * 4 + c];
            qa[ks][0] = x0.x;   // row g,   k 2c,2c+1
            qa[ks][1] = x1.x;   // row g+8, k 2c,2c+1
            qa[ks][2] = x0.y;   // row g,   k 2c+8,2c+9
            qa[ks][3] = x1.y;   // row g+8, k 2c+8,2c+9
        }
    }

    float d[24][4];
#pragma unroll
    for (int t = 0; t < 24; t++)
#pragma unroll
        for (int j = 0; j < 4; j++) d[t][j] = 0.f;
    float rs0 = 0.f, rs1 = 0.f;

    for (int i = 0; i < NCHUNK; i++) {
        const int buf = i & 1;

        if (i + 1 < NCHUNK) {
            const int nb = 1 - buf;
            const int k0 = (i + 1) * CHK;
            {
                int row = tid >> 3, q = tid & 7;
                cp_async16(sb + (KS_H + nb * CHK * QSTR_H + row * QSTR_H + q * 8) * 2,
                           &g_Kh[(qrow0 + k0 + row) * 64 + q * 8], (k0 + row) < NN);
            }
#pragma unroll
            for (int p = 0; p < 3; p++) {
                int idx = tid + 256 * p;
                int n = idx >> 2, q = idx & 3;
                cp_async16(sb + (VT_H + nb * NSLC * VSTR_H + n * VSTR_H + q * 8) * 2,
                           &g_VTh[(size_t)(ns * NSLC + n) * 2048 + k0 + q * 8], true);
            }
            cp_commit();
        }

        // ---- mma1: S = Q K^T  (4 k-groups x 4 n-tiles) ----
        const uint2* Kp = (const uint2*)(smh + KS_H + buf * CHK * QSTR_H);
        float s[4][4];
#pragma unroll
        for (int t = 0; t < 4; t++)
#pragma unroll
            for (int j = 0; j < 4; j++) s[t][j] = 0.f;

#pragma unroll
        for (int ks = 0; ks < 4; ks++) {
#pragma unroll
            for (int nt = 0; nt < 4; nt++) {
                uint2 kb = Kp[(8 * nt + g) * (QSTR_H / 4) + ks * 4 + c];
                mma16n8k16h(s[nt], qa[ks][0], qa[ks][1], qa[ks][2], qa[ks][3],
                            kb.x, kb.y);
            }
        }

        // ---- fused exp + rowsum + mma2 (P: C-frag -> A-frag, in regs) ----
        const uint2* Vp = (const uint2*)(smh + VT_H + buf * NSLC * VSTR_H);
#pragma unroll
        for (int ks2 = 0; ks2 < 2; ks2++) {
            const int t0 = 2 * ks2, t1 = t0 + 1;
            float p00 = __expf(s[t0][0] * SCALE);   // row g,   key 8t0+2c
            float p01 = __expf(s[t0][1] * SCALE);   // row g,   key 8t0+2c+1
            float p02 = __expf(s[t0][2] * SCALE);   // row g+8, key 8t0+2c
            float p03 = __expf(s[t0][3] * SCALE);
            float p10 = __expf(s[t1][0] * SCALE);   // row g,   key 8t1+2c
            float p11 = __expf(s[t1][1] * SCALE);
            float p12 = __expf(s[t1][2] * SCALE);
            float p13 = __expf(s[t1][3] * SCALE);
            if (i == NCHUNK - 1) {
                int kc0 = i * CHK + 8 * t0 + 2 * c;
                int kc1 = i * CHK + 8 * t1 + 2 * c;
                if (kc0     >= NN) { p00 = 0.f; p02 = 0.f; }
                if (kc0 + 1 >= NN) { p01 = 0.f; p03 = 0.f; }
                if (kc1     >= NN) { p10 = 0.f; p12 = 0.f; }
                if (kc1 + 1 >= NN) { p11 = 0.f; p13 = 0.f; }
            }
            rs0 += p00 + p01 + p10 + p11;
            rs1 += p02 + p03 + p12 + p13;
            // A-fragment: a0 row g keys {2c,2c+1}; a2 keys {2c+8,2c+9} (=tile t1)
            uint32_t a0 = pack_f16(p00, p01);
            uint32_t a1 = pack_f16(p02, p03);
            uint32_t a2 = pack_f16(p10, p11);
            uint32_t a3 = pack_f16(p12, p13);
#pragma unroll
            for (int nt = 0; nt < 24; nt++) {
                uint2 vb = Vp[(8 * nt + g) * (VSTR_H / 4) + ks2 * 4 + c];
                mma16n8k16h(d[nt], a0, a1, a2, a3, vb.x, vb.y);
            }
        }

        cp_wait0();
        __syncthreads();
    }

    // ---- epilogue ----
    rs0 += __shfl_xor_sync(0xffffffffu, rs0, 1);
    rs0 += __shfl_xor_sync(0xffffffffu, rs0, 2);
    rs1 += __shfl_xor_sync(0xffffffffu, rs1, 1);
    rs1 += __shfl_xor_sync(0xffffffffu, rs1, 2);
    const float inv0 = 1.f / rs0, inv1 = 1.f / rs1;

    const int r0 = n0 + mr + g;
    const int r1 = r0 + 8;
    float* o0 = out + (qrow0 + r0) * 384 + ns * NSLC + 2 * c;
    float* o1 = out + (qrow0 + r1) * 384 + ns * NSLC + 2 * c;
#pragma unroll
    for (int nt = 0; nt < 24; nt++) {
        if (r0 < NN) *(float2*)(o0 + 8 * nt) = make_float2(d[nt][0] * inv0, d[nt][1] * inv0);
        if (r1 < NN) *(float2*)(o1 + 8 * nt) = make_float2(d[nt][2] * inv1, d[nt][3] * inv1);
    }
}

// ===========================================================================
// Kernel 3: time-attention + broadcast add, vectorized (1 read + 1 write of
// each row, all float4). Deterministic (no float atomics).
// ===========================================================================
__global__ __launch_bounds__(256) void k_time(
    const float* __restrict__ x, const float* __restrict__ Win,
    float* __restrict__ out)
{
    const int wid = threadIdx.x >> 5, lane = threadIdx.x & 31;
    const long node = (long)blockIdx.x * 8 + wid;
    __shared__ float qs[8][16];
    __shared__ float sp[8][97];    // 96 partials + pad

    const float* xl = x + node * 384 + 368;
    float4* dat4 = (float4*)(out + node * 384);

    if (lane < 16) {
        float q = 0.f;
#pragma unroll
        for (int d = 0; d < 16; d++) q += xl[d] * Win[d * 16 + lane];
        qs[wid][lane] = q;
    }
    __syncwarp();

    // each lane: 3 float4 (kept in regs), partial dot vs q
    float4 v[3];
#pragma unroll
    for (int p = 0; p < 3; p++) {
        int idx = 3 * lane + p;
        v[p] = dat4[idx];
        int db = (idx & 3) * 4;
        sp[wid][idx] = v[p].x * qs[wid][db]     + v[p].y * qs[wid][db + 1]
                     + v[p].z * qs[wid][db + 2] + v[p].w * qs[wid][db + 3];
    }
    __syncwarp();

    // att[t] = sum of 4 partials (deterministic order)
    float att = -1e30f;
    if (lane < 24) {
        const float* pp = &sp[wid][lane * 4];
        att = (pp[0] + pp[1]) + (pp[2] + pp[3]);
    }
    float mx = att;
#pragma unroll
    for (int m = 16; m >= 1; m >>= 1)
        mx = fmaxf(mx, __shfl_xor_sync(0xffffffffu, mx, m));
    float e = (lane < 24) ? __expf(att - mx) : 0.f;
    float s = e;
#pragma unroll
    for (int m = 16; m >= 1; m >>= 1)
        s += __shfl_xor_sync(0xffffffffu, s, m);
    float wgt = e / s;

#pragma unroll
    for (int p = 0; p < 3; p++) {
        int idx = 3 * lane + p;
        float wt = __shfl_sync(0xffffffffu, wgt, idx >> 2);
        dat4[idx] = make_float4(v[p].x + wt, v[p].y + wt, v[p].z + wt, v[p].w + wt);
    }
}

// ===========================================================================
extern "C" void kernel_launch(void* const* d_in, const int* in_sizes, int n_in,
                              void* d_out, int out_size)
{
    const float* x      = (const float*)d_in[0];
    const float* Wq     = (const float*)d_in[1];
    const float* bq     = (const float*)d_in[2];
    const float* Wk     = (const float*)d_in[3];
    const float* bk     = (const float*)d_in[4];
    const float* g0     = (const float*)d_in[5];
    const float* be0    = (const float*)d_in[6];
    const float* g1     = (const float*)d_in[7];
    const float* be1    = (const float*)d_in[8];
    const float* normal = (const float*)d_in[9];
    const float* Win    = (const float*)d_in[10];
    float* out = (float*)d_out;

    cudaFuncSetAttribute(k_proj_mma, cudaFuncAttributeMaxDynamicSharedMemorySize, KP_SMEM);
    cudaFuncSetAttribute(k_attn_mma, cudaFuncAttributeMaxDynamicSharedMemorySize, SMEM_SZ);

    k_proj_mma<<<(BATCH * NN) / 64, 256, KP_SMEM>>>(x, Wq, bq, Wk, bk, g0, be0, g1, be1);
    k_transpose<<<dim3(64, 12), 256>>>(normal);
    k_attn_mma<<<dim3(16, 2, BATCH), 256, SMEM_SZ>>>(out);
    k_time<<<(BATCH * NN) / 8, 256>>>(x, Win, out);
}